// round 15
// baseline (speedup 1.0000x reference)
#include <cuda_runtime.h>
#include <cuda_bf16.h>
#include <cstdint>
#include <math.h>

// Problem constants
#define BB   4
#define SS   512
#define HIDD 2048
#define NHH  4
#define HDD  256
#define NMM  8
#define KDD  1024          // NH*HD
#define HVDD 512
#define VDD  2048          // NH*HVD
#define TOKN 2048          // B*S
#define K3   6144          // 3 * 2048 (split-bf16 expanded K)

// GEMM pipeline: 4-stage ring, BK=32, padded stride 40
#define STG_ELE (128 * 40)                 // bf16 elements per stage per operand
#define DSMEM   (8 * STG_ELE * 2)          // 4 A stages + 4 B stages, bytes = 81920

// ---------------- scratch (device globals; no allocation allowed) ----------
__device__ __align__(128) float g_Q [(size_t)TOKN * KDD];
__device__ __align__(128) float g_Kb[(size_t)TOKN * KDD];
__device__ __align__(128) float g_V [(size_t)TOKN * VDD];
__device__ __align__(128) float g_GP[(size_t)TOKN * VDD];
__device__ float g_wmem[TOKN * NMM];
__device__ int   g_slot[TOKN * NMM];
__device__ float g_beta[TOKN * NHH];
__device__ float g_gd  [TOKN * NHH];
__device__ __align__(128) float g_o2 [2 * (size_t)TOKN * VDD];   // [slot][tok][h][hv]

// active-token lists per (memory, batch)
__device__ int g_cnt [NMM * BB];
__device__ int g_list[NMM * BB * SS];

// bf16 split operands ([hi|lo|hi] for A-side, [hi|hi|lo] for B-side)
__device__ __align__(128) __nv_bfloat16 s_x   [(size_t)TOKN * K3];
__device__ __align__(128) __nv_bfloat16 s_nr  [(size_t)TOKN * K3];
__device__ __align__(128) __nv_bfloat16 s_qkw [(size_t)(2 * KDD) * K3];   // q rows then k rows
__device__ __align__(128) __nv_bfloat16 s_vgw [(size_t)(2 * VDD) * K3];   // v rows then g rows
__device__ __align__(128) __nv_bfloat16 s_ow  [(size_t)HIDD * K3];

// ---------------- device-side buffer selectors ----------------------------
__device__ __forceinline__ __nv_bfloat16* sel_bf16(int id) {
    switch (id) {
        case 0: return s_x;
        case 1: return s_nr;
        case 2: return s_qkw;
        case 3: return s_vgw;
        default: return s_ow;
    }
}

// ---------------- small helpers -------------------------------------------
__device__ __forceinline__ float block_sum_256(float v) {
    #pragma unroll
    for (int o = 16; o; o >>= 1) v += __shfl_down_sync(0xffffffffu, v, o);
    __shared__ float sh[8];
    if ((threadIdx.x & 31) == 0) sh[threadIdx.x >> 5] = v;
    __syncthreads();
    if (threadIdx.x == 0) {
        float t = 0.f;
        #pragma unroll
        for (int i = 0; i < 8; i++) t += sh[i];
        sh[0] = t;
    }
    __syncthreads();
    return sh[0];
}

__device__ __forceinline__ void cp16(void* smem, const void* gmem) {
    unsigned s = (unsigned)__cvta_generic_to_shared(smem);
    asm volatile("cp.async.cg.shared.global [%0], [%1], 16;\n" :: "r"(s), "l"(gmem));
}
__device__ __forceinline__ void cp_commit() { asm volatile("cp.async.commit_group;\n"); }

__device__ __forceinline__ void ldsm4(unsigned* r, const void* p) {
    unsigned s = (unsigned)__cvta_generic_to_shared(p);
    asm volatile("ldmatrix.sync.aligned.m8n8.x4.shared.b16 {%0,%1,%2,%3}, [%4];\n"
        : "=r"(r[0]), "=r"(r[1]), "=r"(r[2]), "=r"(r[3]) : "r"(s));
}
__device__ __forceinline__ void mma16816(float* d, const unsigned* a,
                                         unsigned b0, unsigned b1) {
    asm volatile("mma.sync.aligned.m16n8k16.row.col.f32.bf16.bf16.f32 "
        "{%0,%1,%2,%3}, {%4,%5,%6,%7}, {%8,%9}, {%0,%1,%2,%3};\n"
        : "+f"(d[0]), "+f"(d[1]), "+f"(d[2]), "+f"(d[3])
        : "r"(a[0]), "r"(a[1]), "r"(a[2]), "r"(a[3]), "r"(b0), "r"(b1));
}

// packed 2xfp32 math (FFMA2 path — only reachable via PTX f32x2)
__device__ __forceinline__ void fma2(unsigned long long& d, unsigned long long a,
                                     unsigned long long b, unsigned long long c) {
    asm("fma.rn.f32x2 %0, %1, %2, %3;" : "=l"(d) : "l"(a), "l"(b), "l"(c));
}
__device__ __forceinline__ void mul2(unsigned long long& d, unsigned long long a,
                                     unsigned long long b) {
    asm("mul.rn.f32x2 %0, %1, %2;" : "=l"(d) : "l"(a), "l"(b));
}
__device__ __forceinline__ unsigned long long pack2(float v) {
    unsigned u = __float_as_uint(v);
    unsigned long long r;
    asm("mov.b64 %0, {%1, %1};" : "=l"(r) : "r"(u));
    return r;
}
__device__ __forceinline__ float sum2(unsigned long long v) {
    unsigned lo, hi;
    asm("mov.b64 {%0, %1}, %2;" : "=r"(lo), "=r"(hi) : "l"(v));
    return __uint_as_float(lo) + __uint_as_float(hi);
}

// ---------------- fp32 -> split-bf16 conversion (vectorized) ---------------
__global__ __launch_bounds__(256) void conv_kernel(
    const float* __restrict__ src, int dst_id, int isb, int row_off)
{
    const int row = blockIdx.x;
    const int col = threadIdx.x * 8;
    const float* sp = src + (size_t)row * 2048 + col;
    float4 a0 = *(const float4*)sp;
    float4 a1 = *(const float4*)(sp + 4);
    float v[8] = {a0.x, a0.y, a0.z, a0.w, a1.x, a1.y, a1.z, a1.w};

    unsigned hip[4], lop[4];
    #pragma unroll
    for (int j = 0; j < 4; j++) {
        __nv_bfloat16 h0 = __float2bfloat16(v[2 * j]);
        __nv_bfloat16 h1 = __float2bfloat16(v[2 * j + 1]);
        __nv_bfloat16 l0 = __float2bfloat16(v[2 * j]     - __bfloat162float(h0));
        __nv_bfloat16 l1 = __float2bfloat16(v[2 * j + 1] - __bfloat162float(h1));
        __nv_bfloat162 hh; hh.x = h0; hh.y = h1;
        __nv_bfloat162 ll; ll.x = l0; ll.y = l1;
        hip[j] = *(unsigned*)&hh;
        lop[j] = *(unsigned*)&ll;
    }
    uint4 HI = make_uint4(hip[0], hip[1], hip[2], hip[3]);
    uint4 LO = make_uint4(lop[0], lop[1], lop[2], lop[3]);

    __nv_bfloat16* d = sel_bf16(dst_id) + (size_t)(row_off + row) * K3;
    *(uint4*)&d[col]        = HI;
    *(uint4*)&d[2048 + col] = isb ? HI : LO;
    *(uint4*)&d[4096 + col] = isb ? LO : HI;
}

// ---------------- bf16 tensor-core GEMM: C = act(A' @ W'^T) ---------------
// BM=BN=128, BK=32, 4 warps (2x2, 64x64 warp tile), 2 CTAs/SM.
// 4-stage cp.async ring, wait_group 2, one barrier per iteration. (R11 config)
__global__ __launch_bounds__(128, 2) void bgemm_kernel(
    int a_id, int w_id, int mode, float* ext_c)
{
    const int K = K3;
    const int NIT = K / 32;               // 192
    const __nv_bfloat16* A = sel_bf16(a_id);
    const __nv_bfloat16* W = sel_bf16(w_id);

    extern __shared__ __nv_bfloat16 dyn[];

    const int tid  = threadIdx.x;
    const int lane = tid & 31;
    const int w    = tid >> 5;
    const int m0 = blockIdx.y * 128, n0 = blockIdx.x * 128;
    const int wm = (w & 1) * 64;
    const int wn = (w >> 1) * 64;

    float* C; int act, cw, coff;
    if (mode == 0) {
        if (n0 < 1024) { C = g_Q;  act = 1; cw = 1024; coff = 0; }
        else           { C = g_Kb; act = 1; cw = 1024; coff = 1024; }
    } else if (mode == 1) {
        if (n0 < 2048) { C = g_V;  act = 1; cw = 2048; coff = 0; }
        else           { C = g_GP; act = 0; cw = 2048; coff = 2048; }
    } else { C = ext_c; act = 0; cw = 2048; coff = 0; }

    const __nv_bfloat16* Ab = A + (size_t)m0 * K;
    const __nv_bfloat16* Wb = W + (size_t)n0 * K;

    int lr[4], lc[4];
    #pragma unroll
    for (int j = 0; j < 4; j++) {
        int ci = tid + j * 128;
        lr[j] = ci >> 2;
        lc[j] = (ci & 3) * 8;
    }

    auto load_stage = [&](int it, int buf) {
        const int k0 = it * 32;
        __nv_bfloat16* as = dyn + buf * STG_ELE;
        __nv_bfloat16* bs = dyn + (4 + buf) * STG_ELE;
        #pragma unroll
        for (int j = 0; j < 4; j++) {
            cp16(as + lr[j] * 40 + lc[j], Ab + (size_t)lr[j] * K + k0 + lc[j]);
            cp16(bs + lr[j] * 40 + lc[j], Wb + (size_t)lr[j] * K + k0 + lc[j]);
        }
        cp_commit();
    };

    float acc[4][8][4];
    #pragma unroll
    for (int i = 0; i < 4; i++)
        #pragma unroll
        for (int j = 0; j < 8; j++)
            #pragma unroll
            for (int q = 0; q < 4; q++) acc[i][j][q] = 0.f;

    load_stage(0, 0);
    load_stage(1, 1);
    load_stage(2, 2);

    const int a_row = lane & 15;
    const int a_cs  = (lane >> 4) << 3;
    const int b_row = ((lane >> 4) & 1) * 8 + (lane & 7);
    const int b_cs  = ((lane >> 3) & 1) << 3;

    for (int it = 0; it < NIT; it++) {
        asm volatile("cp.async.wait_group 2;\n" ::: "memory");
        __syncthreads();
        if (it + 3 < NIT) load_stage(it + 3, (it + 3) & 3);

        const int buf = it & 3;
        const __nv_bfloat16* as = dyn + buf * STG_ELE;
        const __nv_bfloat16* bs = dyn + (4 + buf) * STG_ELE;
        #pragma unroll
        for (int kk = 0; kk < 32; kk += 16) {
            unsigned af[4][4], bq[4][4];
            #pragma unroll
            for (int mi = 0; mi < 4; mi++)
                ldsm4(af[mi], as + (wm + mi * 16 + a_row) * 40 + kk + a_cs);
            #pragma unroll
            for (int nj = 0; nj < 4; nj++)
                ldsm4(bq[nj], bs + (wn + nj * 16 + b_row) * 40 + kk + b_cs);
            #pragma unroll
            for (int mi = 0; mi < 4; mi++)
                #pragma unroll
                for (int nj = 0; nj < 4; nj++) {
                    mma16816(acc[mi][2 * nj],     af[mi], bq[nj][0], bq[nj][1]);
                    mma16816(acc[mi][2 * nj + 1], af[mi], bq[nj][2], bq[nj][3]);
                }
        }
    }

    const int r  = lane >> 2;
    const int cc = (lane & 3) * 2;
    #pragma unroll
    for (int mi = 0; mi < 4; mi++) {
        #pragma unroll
        for (int ni = 0; ni < 8; ni++) {
            int row0 = m0 + wm + mi * 16 + r;
            int col  = n0 + wn + ni * 8 + cc - coff;
            float d0 = acc[mi][ni][0], d1 = acc[mi][ni][1];
            float d2 = acc[mi][ni][2], d3 = acc[mi][ni][3];
            if (act) {
                d0 = d0 / (1.f + expf(-d0));
                d1 = d1 / (1.f + expf(-d1));
                d2 = d2 / (1.f + expf(-d2));
                d3 = d3 / (1.f + expf(-d3));
            }
            *(float2*)&C[(size_t)row0 * cw + col]       = make_float2(d0, d1);
            *(float2*)&C[(size_t)(row0 + 8) * cw + col] = make_float2(d2, d3);
        }
    }
}

// ---------------- stage 1: gate / beta / g --------------------------------
__global__ __launch_bounds__(128) void gate_kernel(
    const float* __restrict__ x, const float* __restrict__ gate_w,
    const float* __restrict__ b_w, const float* __restrict__ a_w,
    const float* __restrict__ A_log, const float* __restrict__ dt_bias)
{
    const int tok = blockIdx.x;
    const float* xr = x + (size_t)tok * HIDD;
    float acc[16];
    #pragma unroll
    for (int i = 0; i < 16; i++) acc[i] = 0.f;
    for (int k = threadIdx.x; k < HIDD; k += 128) {
        float xv = xr[k];
        #pragma unroll
        for (int w = 0; w < 8; w++) acc[w]      += xv * gate_w[w * HIDD + k];
        #pragma unroll
        for (int w = 0; w < 4; w++) acc[8 + w]  += xv * b_w[w * HIDD + k];
        #pragma unroll
        for (int w = 0; w < 4; w++) acc[12 + w] += xv * a_w[w * HIDD + k];
    }
    #pragma unroll
    for (int i = 0; i < 16; i++) {
        #pragma unroll
        for (int o = 16; o; o >>= 1)
            acc[i] += __shfl_down_sync(0xffffffffu, acc[i], o);
    }
    __shared__ float red[16][4];
    const int lane = threadIdx.x & 31, wrp = threadIdx.x >> 5;
    if (lane == 0) {
        #pragma unroll
        for (int i = 0; i < 16; i++) red[i][wrp] = acc[i];
    }
    __syncthreads();
    if (threadIdx.x == 0) {
        float s[16];
        #pragma unroll
        for (int i = 0; i < 16; i++)
            s[i] = red[i][0] + red[i][1] + red[i][2] + red[i][3];
        float mx = s[0];
        #pragma unroll
        for (int i = 1; i < 8; i++) mx = fmaxf(mx, s[i]);
        float e[8], sum = 0.f;
        #pragma unroll
        for (int i = 0; i < 8; i++) { e[i] = expf(s[i] - mx); sum += e[i]; }
        float inv = 1.f / sum;
        #pragma unroll
        for (int i = 0; i < 8; i++) e[i] *= inv;
        int i1 = 0; float v1 = e[0];
        #pragma unroll
        for (int i = 1; i < 8; i++) if (e[i] > v1) { v1 = e[i]; i1 = i; }
        int i2 = -1; float v2 = -1.f;
        #pragma unroll
        for (int i = 0; i < 8; i++) if (i != i1 && e[i] > v2) { v2 = e[i]; i2 = i; }
        float tot = v1 + v2;
        #pragma unroll
        for (int m = 0; m < NMM; m++) { g_wmem[tok * NMM + m] = 0.f; g_slot[tok * NMM + m] = 0; }
        g_wmem[tok * NMM + i1] = v1 / tot; g_slot[tok * NMM + i1] = 0;
        g_wmem[tok * NMM + i2] = v2 / tot; g_slot[tok * NMM + i2] = 1;
        #pragma unroll
        for (int h = 0; h < NHH; h++) {
            g_beta[tok * NHH + h] = 1.f / (1.f + expf(-s[8 + h]));
            float z = s[12 + h] + dt_bias[h];
            float sp = (z > 20.f) ? z : log1pf(expf(z));
            g_gd[tok * NHH + h] = -expf(A_log[h]) * sp;
        }
    }
}

// ---------------- build compact active-token lists per (m, b) -------------
__global__ __launch_bounds__(32) void buildlist_kernel()
{
    const int mb = blockIdx.x;            // m*4 + b
    const int m = mb >> 2;
    const int b = mb & 3;
    const int lane = threadIdx.x;
    int cnt = 0;
    for (int s0 = 0; s0 < SS; s0 += 32) {
        const int s = s0 + lane;
        const float w = g_wmem[(b * SS + s) * NMM + m];
        const unsigned msk = __ballot_sync(0xffffffffu, w != 0.f);
        if (w != 0.f) {
            int pos = cnt + __popc(msk & ((1u << lane) - 1u));
            g_list[mb * SS + pos] = s;
        }
        cnt += __popc(msk);
    }
    if (lane == 0) g_cnt[mb] = cnt;
}

// ---------------- l2norm over HD per (tok, head); q also * HD^-0.5 --------
__global__ __launch_bounds__(256) void l2norm_kernel()
{
    const int grp = blockIdx.x;                 // tok*NH + h
    float* buf = (blockIdx.y == 0) ? g_Q : g_Kb;
    const size_t base = (size_t)grp * HDD;
    float v = buf[base + threadIdx.x];
    float ss = block_sum_256(v * v);
    float sc = 1.f / fmaxf(sqrtf(ss), 1e-12f);
    if (blockIdx.y == 0) sc *= 0.0625f;         // HD^-0.5 = 1/16
    buf[base + threadIdx.x] = v * sc;
}

// ---------------- gated delta-rule recurrence -------------------------------
// Lane-quad mapping: c = t>>2 (column), gq = t&3 (k-block). Reductions are
// shfl_xor butterflies within the quad -> ONE barrier per step.
// 3-buffer staging ring (write target last read 2 steps ago, fenced by the
// previous step's barrier). k/q blocks padded to 17 float4s: banks
// (4*gq + 2i) mod 32 -> conflict-free with 8-way broadcast.
__global__ __launch_bounds__(256) void recur_kernel()
{
    const int id = blockIdx.x;
    const int m = id >> 4;
    const int b = (id >> 2) & 3;
    const int h = id & 3;
    const int vs = blockIdx.y * 64;
    const int t = threadIdx.x;
    const int c  = t >> 2;               // column 0..63
    const int gq = t & 3;                // k-block 0..3
    const int mb = (m << 2) | b;

    __shared__ float4 kq[3][136];        // 8 blocks (4 k + 4 q) x 17 float4

    unsigned long long hreg[32];
    #pragma unroll
    for (int i = 0; i < 32; i++) hreg[i] = 0ull;

    const int n_act = g_cnt[mb];
    const int* lst = g_list + mb * SS;
    if (n_act == 0) return;

    auto issue_load = [&](int tok, int buf) {
        if (t < 128) {
            const int blk = t >> 4;      // 0..7
            const int idx = t & 15;
            const float* src = (blk < 4)
                ? (g_Kb + (size_t)tok * KDD + h * HDD + (blk * 16 + idx) * 4)
                : (g_Q  + (size_t)tok * KDD + h * HDD + ((blk - 4) * 16 + idx) * 4);
            cp16(&kq[buf][blk * 17 + idx], src);
        }
        cp_commit();
    };

    int tok_c = b * SS + lst[0];
    issue_load(tok_c, 0);
    float w_c   = g_wmem[tok_c * NMM + m];
    int   slt_c = g_slot[tok_c * NMM + m];
    float gd_c  = g_gd  [tok_c * NHH + h];
    float bet_c = g_beta[tok_c * NHH + h];
    float vt_c  = g_V[(size_t)tok_c * VDD + h * HVDD + vs + c];

    for (int ii = 0; ii < n_act; ii++) {
        const int cur = ii % 3;
        const bool hn = (ii + 1 < n_act);
        int tok_n = 0, slt_n = 0;
        float w_n = 0.f, gd_n = 0.f, bet_n = 0.f, vt_n = 0.f;
        if (hn) {
            tok_n = b * SS + lst[ii + 1];
            issue_load(tok_n, (ii + 1) % 3);
            w_n   = g_wmem[tok_n * NMM + m];
            slt_n = g_slot[tok_n * NMM + m];
            gd_n  = g_gd  [tok_n * NHH + h];
            bet_n = g_beta[tok_n * NHH + h];
            vt_n  = g_V[(size_t)tok_n * VDD + h * HVDD + vs + c];
            asm volatile("cp.async.wait_group 1;\n" ::: "memory");
        } else {
            asm volatile("cp.async.wait_group 0;\n" ::: "memory");
        }
        __syncthreads();                 // kq[cur] visible; prior reads fenced

        const float eg = expf(gd_c);
        const unsigned long long* kp2 = (const unsigned long long*)&kq[cur][gq * 17];
        const unsigned long long* qp2 = (const unsigned long long*)&kq[cur][(4 + gq) * 17];

        unsigned long long p2 = 0ull;
        #pragma unroll
        for (int i = 0; i < 32; i++) fma2(p2, hreg[i], kp2[i], p2);
        float p = sum2(p2);
        p += __shfl_xor_sync(0xffffffffu, p, 1);
        p += __shfl_xor_sync(0xffffffffu, p, 2);

        float pred = eg * p;
        float vn = bet_c * (vt_c - pred);

        const unsigned long long eg2 = pack2(eg);
        const unsigned long long vn2 = pack2(vn);

        unsigned long long o2 = 0ull;
        #pragma unroll
        for (int i = 0; i < 32; i++) {
            unsigned long long kv;
            mul2(kv, kp2[i], vn2);
            fma2(hreg[i], hreg[i], eg2, kv);
            fma2(o2, hreg[i], qp2[i], o2);
        }
        float o = sum2(o2);
        o += __shfl_xor_sync(0xffffffffu, o, 1);
        o += __shfl_xor_sync(0xffffffffu, o, 2);

        if (gq == 0) {
            g_o2[(size_t)slt_c * TOKN * VDD + (size_t)tok_c * VDD + h * HVDD + vs + c]
                = w_c * o;
        }

        tok_c = tok_n; w_c = w_n; slt_c = slt_n;
        gd_c = gd_n; bet_c = bet_n; vt_c = vt_n;
    }
}

// ---------------- gated RMSNorm, fused split-bf16 output -------------------
__global__ __launch_bounds__(256) void rmsnorm_kernel(const float* __restrict__ onw)
{
    const int grp = blockIdx.x;            // tok*NH + h
    const int tok = grp >> 2;
    const int h   = grp & 3;
    const int t = threadIdx.x;
    const size_t base = (size_t)grp * HVDD;
    const size_t sstr = (size_t)TOKN * VDD;
    float v0 = g_o2[base + t]       + g_o2[sstr + base + t];
    float v1 = g_o2[base + t + 256] + g_o2[sstr + base + t + 256];
    float ss = block_sum_256(v0 * v0 + v1 * v1);
    float inv = rsqrtf(ss * (1.f / 512.f) + 1e-6f);
    float gp0 = g_GP[base + t], gp1 = g_GP[base + t + 256];
    float out0 = v0 * inv * onw[t]       / (1.f + expf(-gp0));
    float out1 = v1 * inv * onw[t + 256] / (1.f + expf(-gp1));

    __nv_bfloat16* dst = s_nr + (size_t)tok * K3;
    const int col0 = h * HVDD + t;
    const int col1 = col0 + 256;
    __nv_bfloat16 hi0 = __float2bfloat16(out0);
    __nv_bfloat16 lo0 = __float2bfloat16(out0 - __bfloat162float(hi0));
    __nv_bfloat16 hi1 = __float2bfloat16(out1);
    __nv_bfloat16 lo1 = __float2bfloat16(out1 - __bfloat162float(hi1));
    dst[col0] = hi0;  dst[VDD + col0] = lo0;  dst[2 * VDD + col0] = hi0;
    dst[col1] = hi1;  dst[VDD + col1] = lo1;  dst[2 * VDD + col1] = hi1;
}

// ---------------- launcher -------------------------------------------------
extern "C" void kernel_launch(void* const* d_in, const int* in_sizes, int n_in,
                              void* d_out, int out_size)
{
    const float* x        = (const float*)d_in[0];
    const float* gate_w   = (const float*)d_in[1];
    const float* q_w      = (const float*)d_in[2];
    const float* k_w      = (const float*)d_in[3];
    const float* v_w      = (const float*)d_in[4];
    const float* b_w      = (const float*)d_in[5];
    const float* a_w      = (const float*)d_in[6];
    const float* g_w      = (const float*)d_in[7];
    const float* o_w      = (const float*)d_in[8];
    const float* A_log    = (const float*)d_in[9];
    const float* dt_bias  = (const float*)d_in[10];
    const float* o_norm_w = (const float*)d_in[11];
    float* out = (float*)d_out;

    static cudaStream_t s1 = nullptr, s2 = nullptr;
    static cudaEvent_t evRoot = nullptr, evX = nullptr, evVG = nullptr, evS2 = nullptr;
    if (s1 == nullptr) {
        cudaStreamCreateWithFlags(&s1, cudaStreamNonBlocking);
        cudaStreamCreateWithFlags(&s2, cudaStreamNonBlocking);
        cudaEventCreateWithFlags(&evRoot, cudaEventDisableTiming);
        cudaEventCreateWithFlags(&evX,    cudaEventDisableTiming);
        cudaEventCreateWithFlags(&evVG,   cudaEventDisableTiming);
        cudaEventCreateWithFlags(&evS2,   cudaEventDisableTiming);
        cudaFuncSetAttribute(bgemm_kernel, cudaFuncAttributeMaxDynamicSharedMemorySize, DSMEM);
    }

    cudaEventRecord(evRoot, 0);
    cudaStreamWaitEvent(s1, evRoot, 0);
    cudaStreamWaitEvent(s2, evRoot, 0);

    // stream 0: QK path
    conv_kernel<<<TOKN, 256, 0, 0>>>(x, 0, 0, 0);            // s_x
    cudaEventRecord(evX, 0);
    conv_kernel<<<KDD, 256, 0, 0>>>(q_w, 2, 1, 0);
    conv_kernel<<<KDD, 256, 0, 0>>>(k_w, 2, 1, KDD);
    bgemm_kernel<<<dim3(2 * KDD / 128, TOKN / 128), 128, DSMEM, 0>>>(0, 2, 0, nullptr);
    l2norm_kernel<<<dim3(TOKN * NHH, 2), 256, 0, 0>>>();

    // stream s1: VG path
    conv_kernel<<<VDD, 256, 0, s1>>>(v_w, 3, 1, 0);
    conv_kernel<<<VDD, 256, 0, s1>>>(g_w, 3, 1, VDD);
    cudaStreamWaitEvent(s1, evX, 0);
    bgemm_kernel<<<dim3(2 * VDD / 128, TOKN / 128), 128, DSMEM, s1>>>(0, 3, 1, nullptr);
    cudaEventRecord(evVG, s1);

    // stream s2: gate / routing lists / output-weight conversion
    gate_kernel<<<TOKN, 128, 0, s2>>>(x, gate_w, b_w, a_w, A_log, dt_bias);
    buildlist_kernel<<<NMM * BB, 32, 0, s2>>>();
    conv_kernel<<<HIDD, 256, 0, s2>>>(o_w, 4, 1, 0);
    cudaEventRecord(evS2, s2);

    cudaStreamWaitEvent(0, evVG, 0);
    cudaStreamWaitEvent(0, evS2, 0);

    recur_kernel<<<dim3(NMM * BB * NHH, HVDD / 64), 256, 0, 0>>>();
    rmsnorm_kernel<<<TOKN * NHH, 256, 0, 0>>>(o_norm_w);
    bgemm_kernel<<<dim3(HIDD / 128, TOKN / 128), 128, DSMEM, 0>>>(1, 4, 2, out);
}

// round 16
// speedup vs baseline: 1.3005x; 1.3005x over previous
#include <cuda_runtime.h>
#include <cuda_bf16.h>
#include <cstdint>
#include <math.h>

// Problem constants
#define BB   4
#define SS   512
#define HIDD 2048
#define NHH  4
#define HDD  256
#define NMM  8
#define KDD  1024          // NH*HD
#define HVDD 512
#define VDD  2048          // NH*HVD
#define TOKN 2048          // B*S
#define K3   6144          // 3 * 2048 (split-bf16 expanded K)

// GEMM pipeline: 4-stage ring, BK=32, padded stride 40
#define STG_ELE (128 * 40)                 // bf16 elements per stage per operand
#define DSMEM   (8 * STG_ELE * 2)          // 4 A stages + 4 B stages, bytes = 81920

// ---------------- scratch (device globals; no allocation allowed) ----------
__device__ __align__(128) float g_Q [(size_t)TOKN * KDD];
__device__ __align__(128) float g_Kb[(size_t)TOKN * KDD];
__device__ __align__(128) float g_V [(size_t)TOKN * VDD];
__device__ __align__(128) float g_GP[(size_t)TOKN * VDD];
__device__ float g_wmem[TOKN * NMM];
__device__ int   g_slot[TOKN * NMM];
__device__ float g_beta[TOKN * NHH];
__device__ float g_gd  [TOKN * NHH];
__device__ __align__(128) float g_o2 [2 * (size_t)TOKN * VDD];   // [slot][tok][h][hv]

// active-token lists per (memory, batch)
__device__ int g_cnt [NMM * BB];
__device__ int g_list[NMM * BB * SS];

// bf16 split operands ([hi|lo|hi] for A-side, [hi|hi|lo] for B-side)
__device__ __align__(128) __nv_bfloat16 s_x   [(size_t)TOKN * K3];
__device__ __align__(128) __nv_bfloat16 s_nr  [(size_t)TOKN * K3];
__device__ __align__(128) __nv_bfloat16 s_qkw [(size_t)(2 * KDD) * K3];   // q rows then k rows
__device__ __align__(128) __nv_bfloat16 s_vgw [(size_t)(2 * VDD) * K3];   // v rows then g rows
__device__ __align__(128) __nv_bfloat16 s_ow  [(size_t)HIDD * K3];

// ---------------- device-side buffer selectors ----------------------------
__device__ __forceinline__ __nv_bfloat16* sel_bf16(int id) {
    switch (id) {
        case 0: return s_x;
        case 1: return s_nr;
        case 2: return s_qkw;
        case 3: return s_vgw;
        default: return s_ow;
    }
}

// ---------------- small helpers -------------------------------------------
__device__ __forceinline__ float block_sum_256(float v) {
    #pragma unroll
    for (int o = 16; o; o >>= 1) v += __shfl_down_sync(0xffffffffu, v, o);
    __shared__ float sh[8];
    if ((threadIdx.x & 31) == 0) sh[threadIdx.x >> 5] = v;
    __syncthreads();
    if (threadIdx.x == 0) {
        float t = 0.f;
        #pragma unroll
        for (int i = 0; i < 8; i++) t += sh[i];
        sh[0] = t;
    }
    __syncthreads();
    return sh[0];
}

__device__ __forceinline__ void cp16(void* smem, const void* gmem) {
    unsigned s = (unsigned)__cvta_generic_to_shared(smem);
    asm volatile("cp.async.cg.shared.global [%0], [%1], 16;\n" :: "r"(s), "l"(gmem));
}
__device__ __forceinline__ void cp_commit() { asm volatile("cp.async.commit_group;\n"); }

__device__ __forceinline__ void ldsm4(unsigned* r, const void* p) {
    unsigned s = (unsigned)__cvta_generic_to_shared(p);
    asm volatile("ldmatrix.sync.aligned.m8n8.x4.shared.b16 {%0,%1,%2,%3}, [%4];\n"
        : "=r"(r[0]), "=r"(r[1]), "=r"(r[2]), "=r"(r[3]) : "r"(s));
}
__device__ __forceinline__ void mma16816(float* d, const unsigned* a,
                                         unsigned b0, unsigned b1) {
    asm volatile("mma.sync.aligned.m16n8k16.row.col.f32.bf16.bf16.f32 "
        "{%0,%1,%2,%3}, {%4,%5,%6,%7}, {%8,%9}, {%0,%1,%2,%3};\n"
        : "+f"(d[0]), "+f"(d[1]), "+f"(d[2]), "+f"(d[3])
        : "r"(a[0]), "r"(a[1]), "r"(a[2]), "r"(a[3]), "r"(b0), "r"(b1));
}

// packed 2xfp32 math (FFMA2 path — only reachable via PTX f32x2)
__device__ __forceinline__ void fma2(unsigned long long& d, unsigned long long a,
                                     unsigned long long b, unsigned long long c) {
    asm("fma.rn.f32x2 %0, %1, %2, %3;" : "=l"(d) : "l"(a), "l"(b), "l"(c));
}
__device__ __forceinline__ void mul2(unsigned long long& d, unsigned long long a,
                                     unsigned long long b) {
    asm("mul.rn.f32x2 %0, %1, %2;" : "=l"(d) : "l"(a), "l"(b));
}
__device__ __forceinline__ unsigned long long pack2(float v) {
    unsigned u = __float_as_uint(v);
    unsigned long long r;
    asm("mov.b64 %0, {%1, %1};" : "=l"(r) : "r"(u));
    return r;
}
__device__ __forceinline__ float sum2(unsigned long long v) {
    unsigned lo, hi;
    asm("mov.b64 {%0, %1}, %2;" : "=r"(lo), "=r"(hi) : "l"(v));
    return __uint_as_float(lo) + __uint_as_float(hi);
}

// ---------------- fp32 -> split-bf16 conversion (vectorized) ---------------
__global__ __launch_bounds__(256) void conv_kernel(
    const float* __restrict__ src, int dst_id, int isb, int row_off)
{
    const int row = blockIdx.x;
    const int col = threadIdx.x * 8;
    const float* sp = src + (size_t)row * 2048 + col;
    float4 a0 = *(const float4*)sp;
    float4 a1 = *(const float4*)(sp + 4);
    float v[8] = {a0.x, a0.y, a0.z, a0.w, a1.x, a1.y, a1.z, a1.w};

    unsigned hip[4], lop[4];
    #pragma unroll
    for (int j = 0; j < 4; j++) {
        __nv_bfloat16 h0 = __float2bfloat16(v[2 * j]);
        __nv_bfloat16 h1 = __float2bfloat16(v[2 * j + 1]);
        __nv_bfloat16 l0 = __float2bfloat16(v[2 * j]     - __bfloat162float(h0));
        __nv_bfloat16 l1 = __float2bfloat16(v[2 * j + 1] - __bfloat162float(h1));
        __nv_bfloat162 hh; hh.x = h0; hh.y = h1;
        __nv_bfloat162 ll; ll.x = l0; ll.y = l1;
        hip[j] = *(unsigned*)&hh;
        lop[j] = *(unsigned*)&ll;
    }
    uint4 HI = make_uint4(hip[0], hip[1], hip[2], hip[3]);
    uint4 LO = make_uint4(lop[0], lop[1], lop[2], lop[3]);

    __nv_bfloat16* d = sel_bf16(dst_id) + (size_t)(row_off + row) * K3;
    *(uint4*)&d[col]        = HI;
    *(uint4*)&d[2048 + col] = isb ? HI : LO;
    *(uint4*)&d[4096 + col] = isb ? LO : HI;
}

// ---------------- bf16 tensor-core GEMM: C = act(A' @ W'^T) ---------------
// BM=BN=128, BK=32, 4 warps (2x2, 64x64 warp tile), 2 CTAs/SM.
// 4-stage cp.async ring, wait_group 2, one barrier per iteration. (R11 config)
__global__ __launch_bounds__(128, 2) void bgemm_kernel(
    int a_id, int w_id, int mode, float* ext_c)
{
    const int K = K3;
    const int NIT = K / 32;               // 192
    const __nv_bfloat16* A = sel_bf16(a_id);
    const __nv_bfloat16* W = sel_bf16(w_id);

    extern __shared__ __nv_bfloat16 dyn[];

    const int tid  = threadIdx.x;
    const int lane = tid & 31;
    const int w    = tid >> 5;
    const int m0 = blockIdx.y * 128, n0 = blockIdx.x * 128;
    const int wm = (w & 1) * 64;
    const int wn = (w >> 1) * 64;

    float* C; int act, cw, coff;
    if (mode == 0) {
        if (n0 < 1024) { C = g_Q;  act = 1; cw = 1024; coff = 0; }
        else           { C = g_Kb; act = 1; cw = 1024; coff = 1024; }
    } else if (mode == 1) {
        if (n0 < 2048) { C = g_V;  act = 1; cw = 2048; coff = 0; }
        else           { C = g_GP; act = 0; cw = 2048; coff = 2048; }
    } else { C = ext_c; act = 0; cw = 2048; coff = 0; }

    const __nv_bfloat16* Ab = A + (size_t)m0 * K;
    const __nv_bfloat16* Wb = W + (size_t)n0 * K;

    int lr[4], lc[4];
    #pragma unroll
    for (int j = 0; j < 4; j++) {
        int ci = tid + j * 128;
        lr[j] = ci >> 2;
        lc[j] = (ci & 3) * 8;
    }

    auto load_stage = [&](int it, int buf) {
        const int k0 = it * 32;
        __nv_bfloat16* as = dyn + buf * STG_ELE;
        __nv_bfloat16* bs = dyn + (4 + buf) * STG_ELE;
        #pragma unroll
        for (int j = 0; j < 4; j++) {
            cp16(as + lr[j] * 40 + lc[j], Ab + (size_t)lr[j] * K + k0 + lc[j]);
            cp16(bs + lr[j] * 40 + lc[j], Wb + (size_t)lr[j] * K + k0 + lc[j]);
        }
        cp_commit();
    };

    float acc[4][8][4];
    #pragma unroll
    for (int i = 0; i < 4; i++)
        #pragma unroll
        for (int j = 0; j < 8; j++)
            #pragma unroll
            for (int q = 0; q < 4; q++) acc[i][j][q] = 0.f;

    load_stage(0, 0);
    load_stage(1, 1);
    load_stage(2, 2);

    const int a_row = lane & 15;
    const int a_cs  = (lane >> 4) << 3;
    const int b_row = ((lane >> 4) & 1) * 8 + (lane & 7);
    const int b_cs  = ((lane >> 3) & 1) << 3;

    for (int it = 0; it < NIT; it++) {
        asm volatile("cp.async.wait_group 2;\n" ::: "memory");
        __syncthreads();
        if (it + 3 < NIT) load_stage(it + 3, (it + 3) & 3);

        const int buf = it & 3;
        const __nv_bfloat16* as = dyn + buf * STG_ELE;
        const __nv_bfloat16* bs = dyn + (4 + buf) * STG_ELE;
        #pragma unroll
        for (int kk = 0; kk < 32; kk += 16) {
            unsigned af[4][4], bq[4][4];
            #pragma unroll
            for (int mi = 0; mi < 4; mi++)
                ldsm4(af[mi], as + (wm + mi * 16 + a_row) * 40 + kk + a_cs);
            #pragma unroll
            for (int nj = 0; nj < 4; nj++)
                ldsm4(bq[nj], bs + (wn + nj * 16 + b_row) * 40 + kk + b_cs);
            #pragma unroll
            for (int mi = 0; mi < 4; mi++)
                #pragma unroll
                for (int nj = 0; nj < 4; nj++) {
                    mma16816(acc[mi][2 * nj],     af[mi], bq[nj][0], bq[nj][1]);
                    mma16816(acc[mi][2 * nj + 1], af[mi], bq[nj][2], bq[nj][3]);
                }
        }
    }

    const int r  = lane >> 2;
    const int cc = (lane & 3) * 2;
    #pragma unroll
    for (int mi = 0; mi < 4; mi++) {
        #pragma unroll
        for (int ni = 0; ni < 8; ni++) {
            int row0 = m0 + wm + mi * 16 + r;
            int col  = n0 + wn + ni * 8 + cc - coff;
            float d0 = acc[mi][ni][0], d1 = acc[mi][ni][1];
            float d2 = acc[mi][ni][2], d3 = acc[mi][ni][3];
            if (act) {
                d0 = d0 / (1.f + expf(-d0));
                d1 = d1 / (1.f + expf(-d1));
                d2 = d2 / (1.f + expf(-d2));
                d3 = d3 / (1.f + expf(-d3));
            }
            *(float2*)&C[(size_t)row0 * cw + col]       = make_float2(d0, d1);
            *(float2*)&C[(size_t)(row0 + 8) * cw + col] = make_float2(d2, d3);
        }
    }
}

// ---------------- stage 1: gate / beta / g --------------------------------
__global__ __launch_bounds__(128) void gate_kernel(
    const float* __restrict__ x, const float* __restrict__ gate_w,
    const float* __restrict__ b_w, const float* __restrict__ a_w,
    const float* __restrict__ A_log, const float* __restrict__ dt_bias)
{
    const int tok = blockIdx.x;
    const float* xr = x + (size_t)tok * HIDD;
    float acc[16];
    #pragma unroll
    for (int i = 0; i < 16; i++) acc[i] = 0.f;
    for (int k = threadIdx.x; k < HIDD; k += 128) {
        float xv = xr[k];
        #pragma unroll
        for (int w = 0; w < 8; w++) acc[w]      += xv * gate_w[w * HIDD + k];
        #pragma unroll
        for (int w = 0; w < 4; w++) acc[8 + w]  += xv * b_w[w * HIDD + k];
        #pragma unroll
        for (int w = 0; w < 4; w++) acc[12 + w] += xv * a_w[w * HIDD + k];
    }
    #pragma unroll
    for (int i = 0; i < 16; i++) {
        #pragma unroll
        for (int o = 16; o; o >>= 1)
            acc[i] += __shfl_down_sync(0xffffffffu, acc[i], o);
    }
    __shared__ float red[16][4];
    const int lane = threadIdx.x & 31, wrp = threadIdx.x >> 5;
    if (lane == 0) {
        #pragma unroll
        for (int i = 0; i < 16; i++) red[i][wrp] = acc[i];
    }
    __syncthreads();
    if (threadIdx.x == 0) {
        float s[16];
        #pragma unroll
        for (int i = 0; i < 16; i++)
            s[i] = red[i][0] + red[i][1] + red[i][2] + red[i][3];
        float mx = s[0];
        #pragma unroll
        for (int i = 1; i < 8; i++) mx = fmaxf(mx, s[i]);
        float e[8], sum = 0.f;
        #pragma unroll
        for (int i = 0; i < 8; i++) { e[i] = expf(s[i] - mx); sum += e[i]; }
        float inv = 1.f / sum;
        #pragma unroll
        for (int i = 0; i < 8; i++) e[i] *= inv;
        int i1 = 0; float v1 = e[0];
        #pragma unroll
        for (int i = 1; i < 8; i++) if (e[i] > v1) { v1 = e[i]; i1 = i; }
        int i2 = -1; float v2 = -1.f;
        #pragma unroll
        for (int i = 0; i < 8; i++) if (i != i1 && e[i] > v2) { v2 = e[i]; i2 = i; }
        float tot = v1 + v2;
        #pragma unroll
        for (int m = 0; m < NMM; m++) { g_wmem[tok * NMM + m] = 0.f; g_slot[tok * NMM + m] = 0; }
        g_wmem[tok * NMM + i1] = v1 / tot; g_slot[tok * NMM + i1] = 0;
        g_wmem[tok * NMM + i2] = v2 / tot; g_slot[tok * NMM + i2] = 1;
        #pragma unroll
        for (int h = 0; h < NHH; h++) {
            g_beta[tok * NHH + h] = 1.f / (1.f + expf(-s[8 + h]));
            float z = s[12 + h] + dt_bias[h];
            float sp = (z > 20.f) ? z : log1pf(expf(z));
            g_gd[tok * NHH + h] = -expf(A_log[h]) * sp;
        }
    }
}

// ---------------- build compact active-token lists per (m, b) -------------
__global__ __launch_bounds__(32) void buildlist_kernel()
{
    const int mb = blockIdx.x;            // m*4 + b
    const int m = mb >> 2;
    const int b = mb & 3;
    const int lane = threadIdx.x;
    int cnt = 0;
    for (int s0 = 0; s0 < SS; s0 += 32) {
        const int s = s0 + lane;
        const float w = g_wmem[(b * SS + s) * NMM + m];
        const unsigned msk = __ballot_sync(0xffffffffu, w != 0.f);
        if (w != 0.f) {
            int pos = cnt + __popc(msk & ((1u << lane) - 1u));
            g_list[mb * SS + pos] = s;
        }
        cnt += __popc(msk);
    }
    if (lane == 0) g_cnt[mb] = cnt;
}

// ---------------- l2norm over HD per (tok, head); q also * HD^-0.5 --------
__global__ __launch_bounds__(256) void l2norm_kernel()
{
    const int grp = blockIdx.x;                 // tok*NH + h
    float* buf = (blockIdx.y == 0) ? g_Q : g_Kb;
    const size_t base = (size_t)grp * HDD;
    float v = buf[base + threadIdx.x];
    float ss = block_sum_256(v * v);
    float sc = 1.f / fmaxf(sqrtf(ss), 1e-12f);
    if (blockIdx.y == 0) sc *= 0.0625f;         // HD^-0.5 = 1/16
    buf[base + threadIdx.x] = v * sc;
}

// ---------------- gated delta-rule recurrence -------------------------------
// R11 layout (c = t&63, gq = t>>6, float4 broadcast reads) with:
//  - 3-buffer kq staging ring (prefetch target last read 2 steps ago)
//  - deferred output flush (part_o of step ii read after step ii+1's top
//    barrier) -> 2 barriers per step instead of 3. Arithmetic identical to R11.
__global__ __launch_bounds__(256) void recur_kernel()
{
    const int id = blockIdx.x;
    const int m = id >> 4;
    const int b = (id >> 2) & 3;
    const int h = id & 3;
    const int vs = blockIdx.y * 64;
    const int t = threadIdx.x;
    const int c = t & 63;
    const int gq = t >> 6;
    const int mb = (m << 2) | b;

    __shared__ float4 kq[3][128];        // rows 0-63: k, rows 64-127: q
    __shared__ float part_p[4][64];
    __shared__ float part_o[4][64];

    unsigned long long hreg[32];
    #pragma unroll
    for (int i = 0; i < 32; i++) hreg[i] = 0ull;

    const int n_act = g_cnt[mb];
    const int* lst = g_list + mb * SS;
    if (n_act == 0) return;

    auto issue_load = [&](int tok, int buf) {
        if (t < 128) {
            const float* src = (t < 64)
                ? (g_Kb + (size_t)tok * KDD + h * HDD + t * 4)
                : (g_Q  + (size_t)tok * KDD + h * HDD + (t - 64) * 4);
            cp16(&kq[buf][t], src);
        }
        cp_commit();
    };

    int tok_c = b * SS + lst[0];
    issue_load(tok_c, 0);
    float w_c   = g_wmem[tok_c * NMM + m];
    int   slt_c = g_slot[tok_c * NMM + m];
    float gd_c  = g_gd  [tok_c * NHH + h];
    float bet_c = g_beta[tok_c * NHH + h];
    float vt_c  = g_V[(size_t)tok_c * VDD + h * HVDD + vs + c];

    int tok_p = 0, slt_p = 0;
    float w_p = 0.f;

    for (int ii = 0; ii < n_act; ii++) {
        const int cur = ii % 3;
        const bool hn = (ii + 1 < n_act);
        int tok_n = 0, slt_n = 0;
        float w_n = 0.f, gd_n = 0.f, bet_n = 0.f, vt_n = 0.f;
        if (hn) {
            tok_n = b * SS + lst[ii + 1];
            issue_load(tok_n, (ii + 1) % 3);
            w_n   = g_wmem[tok_n * NMM + m];
            slt_n = g_slot[tok_n * NMM + m];
            gd_n  = g_gd  [tok_n * NHH + h];
            bet_n = g_beta[tok_n * NHH + h];
            vt_n  = g_V[(size_t)tok_n * VDD + h * HVDD + vs + c];
            asm volatile("cp.async.wait_group 1;\n" ::: "memory");
        } else {
            asm volatile("cp.async.wait_group 0;\n" ::: "memory");
        }
        __syncthreads();                 // top: kq[cur] ready; prev part_o ready

        // deferred flush of step ii-1's output
        if (ii > 0 && t < 64) {
            float ov = part_o[0][c] + part_o[1][c] + part_o[2][c] + part_o[3][c];
            g_o2[(size_t)slt_p * TOKN * VDD + (size_t)tok_p * VDD + h * HVDD + vs + c]
                = w_p * ov;
        }

        const float eg = expf(gd_c);
        const unsigned long long* kp2 = (const unsigned long long*)&kq[cur][gq * 16];
        const unsigned long long* qp2 = (const unsigned long long*)&kq[cur][64 + gq * 16];

        unsigned long long p2 = 0ull;
        #pragma unroll
        for (int i = 0; i < 32; i++) fma2(p2, hreg[i], kp2[i], p2);
        part_p[gq][c] = sum2(p2);
        __syncthreads();                 // mid: part_p ready; part_o reads done

        float pred = eg * (part_p[0][c] + part_p[1][c] + part_p[2][c] + part_p[3][c]);
        float vn = bet_c * (vt_c - pred);

        const unsigned long long eg2 = pack2(eg);
        const unsigned long long vn2 = pack2(vn);

        unsigned long long o2 = 0ull;
        #pragma unroll
        for (int i = 0; i < 32; i++) {
            unsigned long long kv;
            mul2(kv, kp2[i], vn2);
            fma2(hreg[i], hreg[i], eg2, kv);
            fma2(o2, hreg[i], qp2[i], o2);
        }
        part_o[gq][c] = sum2(o2);
        // no barrier: next step's top barrier fences part_o write->read

        tok_p = tok_c; w_p = w_c; slt_p = slt_c;
        tok_c = tok_n; w_c = w_n; slt_c = slt_n;
        gd_c = gd_n; bet_c = bet_n; vt_c = vt_n;
    }

    __syncthreads();
    if (t < 64) {
        float ov = part_o[0][c] + part_o[1][c] + part_o[2][c] + part_o[3][c];
        g_o2[(size_t)slt_p * TOKN * VDD + (size_t)tok_p * VDD + h * HVDD + vs + c]
            = w_p * ov;
    }
}

// ---------------- gated RMSNorm, fused split-bf16 output -------------------
__global__ __launch_bounds__(256) void rmsnorm_kernel(const float* __restrict__ onw)
{
    const int grp = blockIdx.x;            // tok*NH + h
    const int tok = grp >> 2;
    const int h   = grp & 3;
    const int t = threadIdx.x;
    const size_t base = (size_t)grp * HVDD;
    const size_t sstr = (size_t)TOKN * VDD;
    float v0 = g_o2[base + t]       + g_o2[sstr + base + t];
    float v1 = g_o2[base + t + 256] + g_o2[sstr + base + t + 256];
    float ss = block_sum_256(v0 * v0 + v1 * v1);
    float inv = rsqrtf(ss * (1.f / 512.f) + 1e-6f);
    float gp0 = g_GP[base + t], gp1 = g_GP[base + t + 256];
    float out0 = v0 * inv * onw[t]       / (1.f + expf(-gp0));
    float out1 = v1 * inv * onw[t + 256] / (1.f + expf(-gp1));

    __nv_bfloat16* dst = s_nr + (size_t)tok * K3;
    const int col0 = h * HVDD + t;
    const int col1 = col0 + 256;
    __nv_bfloat16 hi0 = __float2bfloat16(out0);
    __nv_bfloat16 lo0 = __float2bfloat16(out0 - __bfloat162float(hi0));
    __nv_bfloat16 hi1 = __float2bfloat16(out1);
    __nv_bfloat16 lo1 = __float2bfloat16(out1 - __bfloat162float(hi1));
    dst[col0] = hi0;  dst[VDD + col0] = lo0;  dst[2 * VDD + col0] = hi0;
    dst[col1] = hi1;  dst[VDD + col1] = lo1;  dst[2 * VDD + col1] = hi1;
}

// ---------------- launcher -------------------------------------------------
extern "C" void kernel_launch(void* const* d_in, const int* in_sizes, int n_in,
                              void* d_out, int out_size)
{
    const float* x        = (const float*)d_in[0];
    const float* gate_w   = (const float*)d_in[1];
    const float* q_w      = (const float*)d_in[2];
    const float* k_w      = (const float*)d_in[3];
    const float* v_w      = (const float*)d_in[4];
    const float* b_w      = (const float*)d_in[5];
    const float* a_w      = (const float*)d_in[6];
    const float* g_w      = (const float*)d_in[7];
    const float* o_w      = (const float*)d_in[8];
    const float* A_log    = (const float*)d_in[9];
    const float* dt_bias  = (const float*)d_in[10];
    const float* o_norm_w = (const float*)d_in[11];
    float* out = (float*)d_out;

    static cudaStream_t s1 = nullptr, s2 = nullptr;
    static cudaEvent_t evRoot = nullptr, evX = nullptr, evVG = nullptr, evS2 = nullptr;
    if (s1 == nullptr) {
        cudaStreamCreateWithFlags(&s1, cudaStreamNonBlocking);
        cudaStreamCreateWithFlags(&s2, cudaStreamNonBlocking);
        cudaEventCreateWithFlags(&evRoot, cudaEventDisableTiming);
        cudaEventCreateWithFlags(&evX,    cudaEventDisableTiming);
        cudaEventCreateWithFlags(&evVG,   cudaEventDisableTiming);
        cudaEventCreateWithFlags(&evS2,   cudaEventDisableTiming);
        cudaFuncSetAttribute(bgemm_kernel, cudaFuncAttributeMaxDynamicSharedMemorySize, DSMEM);
    }

    cudaEventRecord(evRoot, 0);
    cudaStreamWaitEvent(s1, evRoot, 0);
    cudaStreamWaitEvent(s2, evRoot, 0);

    // stream 0: QK path
    conv_kernel<<<TOKN, 256, 0, 0>>>(x, 0, 0, 0);            // s_x
    cudaEventRecord(evX, 0);
    conv_kernel<<<KDD, 256, 0, 0>>>(q_w, 2, 1, 0);
    conv_kernel<<<KDD, 256, 0, 0>>>(k_w, 2, 1, KDD);
    bgemm_kernel<<<dim3(2 * KDD / 128, TOKN / 128), 128, DSMEM, 0>>>(0, 2, 0, nullptr);
    l2norm_kernel<<<dim3(TOKN * NHH, 2), 256, 0, 0>>>();

    // stream s1: VG path
    conv_kernel<<<VDD, 256, 0, s1>>>(v_w, 3, 1, 0);
    conv_kernel<<<VDD, 256, 0, s1>>>(g_w, 3, 1, VDD);
    cudaStreamWaitEvent(s1, evX, 0);
    bgemm_kernel<<<dim3(2 * VDD / 128, TOKN / 128), 128, DSMEM, s1>>>(0, 3, 1, nullptr);
    cudaEventRecord(evVG, s1);

    // stream s2: gate / routing lists / output-weight conversion
    gate_kernel<<<TOKN, 128, 0, s2>>>(x, gate_w, b_w, a_w, A_log, dt_bias);
    buildlist_kernel<<<NMM * BB, 32, 0, s2>>>();
    conv_kernel<<<HIDD, 256, 0, s2>>>(o_w, 4, 1, 0);
    cudaEventRecord(evS2, s2);

    cudaStreamWaitEvent(0, evVG, 0);
    cudaStreamWaitEvent(0, evS2, 0);

    recur_kernel<<<dim3(NMM * BB * NHH, HVDD / 64), 256, 0, 0>>>();
    rmsnorm_kernel<<<TOKN * NHH, 256, 0, 0>>>(o_norm_w);
    bgemm_kernel<<<dim3(HIDD / 128, TOKN / 128), 128, DSMEM, 0>>>(1, 4, 2, out);
}

// round 17
// speedup vs baseline: 1.3137x; 1.0101x over previous
#include <cuda_runtime.h>
#include <cuda_bf16.h>
#include <cstdint>
#include <math.h>

// Problem constants
#define BB   4
#define SS   512
#define HIDD 2048
#define NHH  4
#define HDD  256
#define NMM  8
#define KDD  1024          // NH*HD
#define HVDD 512
#define VDD  2048          // NH*HVD
#define TOKN 2048          // B*S
#define K3   6144          // 3 * 2048 (split-bf16 expanded K)

// GEMM pipeline: 4-stage ring, BK=32, padded stride 40
#define STG_ELE (128 * 40)                 // bf16 elements per stage per operand
#define DSMEM   (8 * STG_ELE * 2)          // 4 A stages + 4 B stages, bytes = 81920

// ---------------- scratch (device globals; no allocation allowed) ----------
__device__ __align__(128) float g_Q [(size_t)TOKN * KDD];
__device__ __align__(128) float g_Kb[(size_t)TOKN * KDD];
__device__ __align__(128) float g_V [(size_t)TOKN * VDD];
__device__ __align__(128) float g_GP[(size_t)TOKN * VDD];
__device__ float g_wmem[TOKN * NMM];
__device__ int   g_slot[TOKN * NMM];
__device__ float g_beta[TOKN * NHH];
__device__ float g_gd  [TOKN * NHH];
__device__ __align__(128) float g_o2 [2 * (size_t)TOKN * VDD];   // [slot][tok][h][hv]

// active-token lists per (memory, batch)
__device__ int g_cnt [NMM * BB];
__device__ int g_list[NMM * BB * SS];

// bf16 split operands ([hi|lo|hi] for A-side, [hi|hi|lo] for B-side)
__device__ __align__(128) __nv_bfloat16 s_x   [(size_t)TOKN * K3];
__device__ __align__(128) __nv_bfloat16 s_nr  [(size_t)TOKN * K3];
__device__ __align__(128) __nv_bfloat16 s_qkw [(size_t)(2 * KDD) * K3];   // q rows then k rows
__device__ __align__(128) __nv_bfloat16 s_vgw [(size_t)(2 * VDD) * K3];   // v rows then g rows
__device__ __align__(128) __nv_bfloat16 s_ow  [(size_t)HIDD * K3];

// ---------------- device-side buffer selectors ----------------------------
__device__ __forceinline__ __nv_bfloat16* sel_bf16(int id) {
    switch (id) {
        case 0: return s_x;
        case 1: return s_nr;
        case 2: return s_qkw;
        case 3: return s_vgw;
        default: return s_ow;
    }
}

// ---------------- small helpers -------------------------------------------
__device__ __forceinline__ float block_sum_256(float v) {
    #pragma unroll
    for (int o = 16; o; o >>= 1) v += __shfl_down_sync(0xffffffffu, v, o);
    __shared__ float sh[8];
    if ((threadIdx.x & 31) == 0) sh[threadIdx.x >> 5] = v;
    __syncthreads();
    if (threadIdx.x == 0) {
        float t = 0.f;
        #pragma unroll
        for (int i = 0; i < 8; i++) t += sh[i];
        sh[0] = t;
    }
    __syncthreads();
    return sh[0];
}

__device__ __forceinline__ void cp16(void* smem, const void* gmem) {
    unsigned s = (unsigned)__cvta_generic_to_shared(smem);
    asm volatile("cp.async.cg.shared.global [%0], [%1], 16;\n" :: "r"(s), "l"(gmem));
}
__device__ __forceinline__ void cp_commit() { asm volatile("cp.async.commit_group;\n"); }

__device__ __forceinline__ void ldsm4(unsigned* r, const void* p) {
    unsigned s = (unsigned)__cvta_generic_to_shared(p);
    asm volatile("ldmatrix.sync.aligned.m8n8.x4.shared.b16 {%0,%1,%2,%3}, [%4];\n"
        : "=r"(r[0]), "=r"(r[1]), "=r"(r[2]), "=r"(r[3]) : "r"(s));
}
__device__ __forceinline__ void mma16816(float* d, const unsigned* a,
                                         unsigned b0, unsigned b1) {
    asm volatile("mma.sync.aligned.m16n8k16.row.col.f32.bf16.bf16.f32 "
        "{%0,%1,%2,%3}, {%4,%5,%6,%7}, {%8,%9}, {%0,%1,%2,%3};\n"
        : "+f"(d[0]), "+f"(d[1]), "+f"(d[2]), "+f"(d[3])
        : "r"(a[0]), "r"(a[1]), "r"(a[2]), "r"(a[3]), "r"(b0), "r"(b1));
}

// packed 2xfp32 math (FFMA2 path — only reachable via PTX f32x2)
__device__ __forceinline__ void fma2(unsigned long long& d, unsigned long long a,
                                     unsigned long long b, unsigned long long c) {
    asm("fma.rn.f32x2 %0, %1, %2, %3;" : "=l"(d) : "l"(a), "l"(b), "l"(c));
}
__device__ __forceinline__ void mul2(unsigned long long& d, unsigned long long a,
                                     unsigned long long b) {
    asm("mul.rn.f32x2 %0, %1, %2;" : "=l"(d) : "l"(a), "l"(b));
}
__device__ __forceinline__ unsigned long long pack2(float v) {
    unsigned u = __float_as_uint(v);
    unsigned long long r;
    asm("mov.b64 %0, {%1, %1};" : "=l"(r) : "r"(u));
    return r;
}
__device__ __forceinline__ float sum2(unsigned long long v) {
    unsigned lo, hi;
    asm("mov.b64 {%0, %1}, %2;" : "=r"(lo), "=r"(hi) : "l"(v));
    return __uint_as_float(lo) + __uint_as_float(hi);
}

// ---------------- fp32 -> split-bf16 conversion (vectorized) ---------------
__global__ __launch_bounds__(256) void conv_kernel(
    const float* __restrict__ src, int dst_id, int isb, int row_off)
{
    const int row = blockIdx.x;
    const int col = threadIdx.x * 8;
    const float* sp = src + (size_t)row * 2048 + col;
    float4 a0 = *(const float4*)sp;
    float4 a1 = *(const float4*)(sp + 4);
    float v[8] = {a0.x, a0.y, a0.z, a0.w, a1.x, a1.y, a1.z, a1.w};

    unsigned hip[4], lop[4];
    #pragma unroll
    for (int j = 0; j < 4; j++) {
        __nv_bfloat16 h0 = __float2bfloat16(v[2 * j]);
        __nv_bfloat16 h1 = __float2bfloat16(v[2 * j + 1]);
        __nv_bfloat16 l0 = __float2bfloat16(v[2 * j]     - __bfloat162float(h0));
        __nv_bfloat16 l1 = __float2bfloat16(v[2 * j + 1] - __bfloat162float(h1));
        __nv_bfloat162 hh; hh.x = h0; hh.y = h1;
        __nv_bfloat162 ll; ll.x = l0; ll.y = l1;
        hip[j] = *(unsigned*)&hh;
        lop[j] = *(unsigned*)&ll;
    }
    uint4 HI = make_uint4(hip[0], hip[1], hip[2], hip[3]);
    uint4 LO = make_uint4(lop[0], lop[1], lop[2], lop[3]);

    __nv_bfloat16* d = sel_bf16(dst_id) + (size_t)(row_off + row) * K3;
    *(uint4*)&d[col]        = HI;
    *(uint4*)&d[2048 + col] = isb ? HI : LO;
    *(uint4*)&d[4096 + col] = isb ? LO : HI;
}

// ---------------- bf16 tensor-core GEMM: C = act(A' @ W'^T) ---------------
// BM=BN=128, BK=32, 4 warps (2x2, 64x64 warp tile), 2 CTAs/SM.
// 4-stage cp.async ring, wait_group 2, one barrier per iteration.
// mode 0: cols [0,1024)->g_Q silu, [1024,2048)->g_Kb silu  (W = s_qkw)
// mode 1: g_V, silu   (W rows at wrow offset in s_vgw)
// mode 3: g_GP, none  (W rows at wrow offset in s_vgw)
// mode 2: ext_c [M,2048], none
__global__ __launch_bounds__(128, 2) void bgemm_kernel(
    int a_id, int w_id, int mode, float* ext_c, int wrow)
{
    const int K = K3;
    const int NIT = K / 32;               // 192
    const __nv_bfloat16* A = sel_bf16(a_id);
    const __nv_bfloat16* W = sel_bf16(w_id) + (size_t)wrow * K3;

    extern __shared__ __nv_bfloat16 dyn[];

    const int tid  = threadIdx.x;
    const int lane = tid & 31;
    const int w    = tid >> 5;
    const int m0 = blockIdx.y * 128, n0 = blockIdx.x * 128;
    const int wm = (w & 1) * 64;
    const int wn = (w >> 1) * 64;

    float* C; int act, cw, coff;
    if (mode == 0) {
        if (n0 < 1024) { C = g_Q;  act = 1; cw = 1024; coff = 0; }
        else           { C = g_Kb; act = 1; cw = 1024; coff = 1024; }
    } else if (mode == 1) {
        C = g_V;  act = 1; cw = 2048; coff = 0;
    } else if (mode == 3) {
        C = g_GP; act = 0; cw = 2048; coff = 0;
    } else { C = ext_c; act = 0; cw = 2048; coff = 0; }

    const __nv_bfloat16* Ab = A + (size_t)m0 * K;
    const __nv_bfloat16* Wb = W + (size_t)n0 * K;

    int lr[4], lc[4];
    #pragma unroll
    for (int j = 0; j < 4; j++) {
        int ci = tid + j * 128;
        lr[j] = ci >> 2;
        lc[j] = (ci & 3) * 8;
    }

    auto load_stage = [&](int it, int buf) {
        const int k0 = it * 32;
        __nv_bfloat16* as = dyn + buf * STG_ELE;
        __nv_bfloat16* bs = dyn + (4 + buf) * STG_ELE;
        #pragma unroll
        for (int j = 0; j < 4; j++) {
            cp16(as + lr[j] * 40 + lc[j], Ab + (size_t)lr[j] * K + k0 + lc[j]);
            cp16(bs + lr[j] * 40 + lc[j], Wb + (size_t)lr[j] * K + k0 + lc[j]);
        }
        cp_commit();
    };

    float acc[4][8][4];
    #pragma unroll
    for (int i = 0; i < 4; i++)
        #pragma unroll
        for (int j = 0; j < 8; j++)
            #pragma unroll
            for (int q = 0; q < 4; q++) acc[i][j][q] = 0.f;

    load_stage(0, 0);
    load_stage(1, 1);
    load_stage(2, 2);

    const int a_row = lane & 15;
    const int a_cs  = (lane >> 4) << 3;
    const int b_row = ((lane >> 4) & 1) * 8 + (lane & 7);
    const int b_cs  = ((lane >> 3) & 1) << 3;

    for (int it = 0; it < NIT; it++) {
        asm volatile("cp.async.wait_group 2;\n" ::: "memory");
        __syncthreads();
        if (it + 3 < NIT) load_stage(it + 3, (it + 3) & 3);

        const int buf = it & 3;
        const __nv_bfloat16* as = dyn + buf * STG_ELE;
        const __nv_bfloat16* bs = dyn + (4 + buf) * STG_ELE;
        #pragma unroll
        for (int kk = 0; kk < 32; kk += 16) {
            unsigned af[4][4], bq[4][4];
            #pragma unroll
            for (int mi = 0; mi < 4; mi++)
                ldsm4(af[mi], as + (wm + mi * 16 + a_row) * 40 + kk + a_cs);
            #pragma unroll
            for (int nj = 0; nj < 4; nj++)
                ldsm4(bq[nj], bs + (wn + nj * 16 + b_row) * 40 + kk + b_cs);
            #pragma unroll
            for (int mi = 0; mi < 4; mi++)
                #pragma unroll
                for (int nj = 0; nj < 4; nj++) {
                    mma16816(acc[mi][2 * nj],     af[mi], bq[nj][0], bq[nj][1]);
                    mma16816(acc[mi][2 * nj + 1], af[mi], bq[nj][2], bq[nj][3]);
                }
        }
    }

    const int r  = lane >> 2;
    const int cc = (lane & 3) * 2;
    #pragma unroll
    for (int mi = 0; mi < 4; mi++) {
        #pragma unroll
        for (int ni = 0; ni < 8; ni++) {
            int row0 = m0 + wm + mi * 16 + r;
            int col  = n0 + wn + ni * 8 + cc - coff;
            float d0 = acc[mi][ni][0], d1 = acc[mi][ni][1];
            float d2 = acc[mi][ni][2], d3 = acc[mi][ni][3];
            if (act) {
                d0 = d0 / (1.f + expf(-d0));
                d1 = d1 / (1.f + expf(-d1));
                d2 = d2 / (1.f + expf(-d2));
                d3 = d3 / (1.f + expf(-d3));
            }
            *(float2*)&C[(size_t)row0 * cw + col]       = make_float2(d0, d1);
            *(float2*)&C[(size_t)(row0 + 8) * cw + col] = make_float2(d2, d3);
        }
    }
}

// ---------------- stage 1: gate / beta / g --------------------------------
__global__ __launch_bounds__(128) void gate_kernel(
    const float* __restrict__ x, const float* __restrict__ gate_w,
    const float* __restrict__ b_w, const float* __restrict__ a_w,
    const float* __restrict__ A_log, const float* __restrict__ dt_bias)
{
    const int tok = blockIdx.x;
    const float* xr = x + (size_t)tok * HIDD;
    float acc[16];
    #pragma unroll
    for (int i = 0; i < 16; i++) acc[i] = 0.f;
    for (int k = threadIdx.x; k < HIDD; k += 128) {
        float xv = xr[k];
        #pragma unroll
        for (int w = 0; w < 8; w++) acc[w]      += xv * gate_w[w * HIDD + k];
        #pragma unroll
        for (int w = 0; w < 4; w++) acc[8 + w]  += xv * b_w[w * HIDD + k];
        #pragma unroll
        for (int w = 0; w < 4; w++) acc[12 + w] += xv * a_w[w * HIDD + k];
    }
    #pragma unroll
    for (int i = 0; i < 16; i++) {
        #pragma unroll
        for (int o = 16; o; o >>= 1)
            acc[i] += __shfl_down_sync(0xffffffffu, acc[i], o);
    }
    __shared__ float red[16][4];
    const int lane = threadIdx.x & 31, wrp = threadIdx.x >> 5;
    if (lane == 0) {
        #pragma unroll
        for (int i = 0; i < 16; i++) red[i][wrp] = acc[i];
    }
    __syncthreads();
    if (threadIdx.x == 0) {
        float s[16];
        #pragma unroll
        for (int i = 0; i < 16; i++)
            s[i] = red[i][0] + red[i][1] + red[i][2] + red[i][3];
        float mx = s[0];
        #pragma unroll
        for (int i = 1; i < 8; i++) mx = fmaxf(mx, s[i]);
        float e[8], sum = 0.f;
        #pragma unroll
        for (int i = 0; i < 8; i++) { e[i] = expf(s[i] - mx); sum += e[i]; }
        float inv = 1.f / sum;
        #pragma unroll
        for (int i = 0; i < 8; i++) e[i] *= inv;
        int i1 = 0; float v1 = e[0];
        #pragma unroll
        for (int i = 1; i < 8; i++) if (e[i] > v1) { v1 = e[i]; i1 = i; }
        int i2 = -1; float v2 = -1.f;
        #pragma unroll
        for (int i = 0; i < 8; i++) if (i != i1 && e[i] > v2) { v2 = e[i]; i2 = i; }
        float tot = v1 + v2;
        #pragma unroll
        for (int m = 0; m < NMM; m++) { g_wmem[tok * NMM + m] = 0.f; g_slot[tok * NMM + m] = 0; }
        g_wmem[tok * NMM + i1] = v1 / tot; g_slot[tok * NMM + i1] = 0;
        g_wmem[tok * NMM + i2] = v2 / tot; g_slot[tok * NMM + i2] = 1;
        #pragma unroll
        for (int h = 0; h < NHH; h++) {
            g_beta[tok * NHH + h] = 1.f / (1.f + expf(-s[8 + h]));
            float z = s[12 + h] + dt_bias[h];
            float sp = (z > 20.f) ? z : log1pf(expf(z));
            g_gd[tok * NHH + h] = -expf(A_log[h]) * sp;
        }
    }
}

// ---------------- build compact active-token lists per (m, b) -------------
__global__ __launch_bounds__(32) void buildlist_kernel()
{
    const int mb = blockIdx.x;            // m*4 + b
    const int m = mb >> 2;
    const int b = mb & 3;
    const int lane = threadIdx.x;
    int cnt = 0;
    for (int s0 = 0; s0 < SS; s0 += 32) {
        const int s = s0 + lane;
        const float w = g_wmem[(b * SS + s) * NMM + m];
        const unsigned msk = __ballot_sync(0xffffffffu, w != 0.f);
        if (w != 0.f) {
            int pos = cnt + __popc(msk & ((1u << lane) - 1u));
            g_list[mb * SS + pos] = s;
        }
        cnt += __popc(msk);
    }
    if (lane == 0) g_cnt[mb] = cnt;
}

// ---------------- l2norm over HD per (tok, head); q also * HD^-0.5 --------
__global__ __launch_bounds__(256) void l2norm_kernel()
{
    const int grp = blockIdx.x;                 // tok*NH + h
    float* buf = (blockIdx.y == 0) ? g_Q : g_Kb;
    const size_t base = (size_t)grp * HDD;
    float v = buf[base + threadIdx.x];
    float ss = block_sum_256(v * v);
    float sc = 1.f / fmaxf(sqrtf(ss), 1e-12f);
    if (blockIdx.y == 0) sc *= 0.0625f;         // HD^-0.5 = 1/16
    buf[base + threadIdx.x] = v * sc;
}

// ---------------- gated delta-rule recurrence -------------------------------
// R11 layout, 3-buffer staging ring, deferred output flush (2 barriers/step).
__global__ __launch_bounds__(256) void recur_kernel()
{
    const int id = blockIdx.x;
    const int m = id >> 4;
    const int b = (id >> 2) & 3;
    const int h = id & 3;
    const int vs = blockIdx.y * 64;
    const int t = threadIdx.x;
    const int c = t & 63;
    const int gq = t >> 6;
    const int mb = (m << 2) | b;

    __shared__ float4 kq[3][128];        // rows 0-63: k, rows 64-127: q
    __shared__ float part_p[4][64];
    __shared__ float part_o[4][64];

    unsigned long long hreg[32];
    #pragma unroll
    for (int i = 0; i < 32; i++) hreg[i] = 0ull;

    const int n_act = g_cnt[mb];
    const int* lst = g_list + mb * SS;
    if (n_act == 0) return;

    auto issue_load = [&](int tok, int buf) {
        if (t < 128) {
            const float* src = (t < 64)
                ? (g_Kb + (size_t)tok * KDD + h * HDD + t * 4)
                : (g_Q  + (size_t)tok * KDD + h * HDD + (t - 64) * 4);
            cp16(&kq[buf][t], src);
        }
        cp_commit();
    };

    int tok_c = b * SS + lst[0];
    issue_load(tok_c, 0);
    float w_c   = g_wmem[tok_c * NMM + m];
    int   slt_c = g_slot[tok_c * NMM + m];
    float gd_c  = g_gd  [tok_c * NHH + h];
    float bet_c = g_beta[tok_c * NHH + h];
    float vt_c  = g_V[(size_t)tok_c * VDD + h * HVDD + vs + c];

    int tok_p = 0, slt_p = 0;
    float w_p = 0.f;

    for (int ii = 0; ii < n_act; ii++) {
        const int cur = ii % 3;
        const bool hn = (ii + 1 < n_act);
        int tok_n = 0, slt_n = 0;
        float w_n = 0.f, gd_n = 0.f, bet_n = 0.f, vt_n = 0.f;
        if (hn) {
            tok_n = b * SS + lst[ii + 1];
            issue_load(tok_n, (ii + 1) % 3);
            w_n   = g_wmem[tok_n * NMM + m];
            slt_n = g_slot[tok_n * NMM + m];
            gd_n  = g_gd  [tok_n * NHH + h];
            bet_n = g_beta[tok_n * NHH + h];
            vt_n  = g_V[(size_t)tok_n * VDD + h * HVDD + vs + c];
            asm volatile("cp.async.wait_group 1;\n" ::: "memory");
        } else {
            asm volatile("cp.async.wait_group 0;\n" ::: "memory");
        }
        __syncthreads();                 // top: kq[cur] ready; prev part_o ready

        if (ii > 0 && t < 64) {
            float ov = part_o[0][c] + part_o[1][c] + part_o[2][c] + part_o[3][c];
            g_o2[(size_t)slt_p * TOKN * VDD + (size_t)tok_p * VDD + h * HVDD + vs + c]
                = w_p * ov;
        }

        const float eg = expf(gd_c);
        const unsigned long long* kp2 = (const unsigned long long*)&kq[cur][gq * 16];
        const unsigned long long* qp2 = (const unsigned long long*)&kq[cur][64 + gq * 16];

        unsigned long long p2 = 0ull;
        #pragma unroll
        for (int i = 0; i < 32; i++) fma2(p2, hreg[i], kp2[i], p2);
        part_p[gq][c] = sum2(p2);
        __syncthreads();                 // mid: part_p ready; part_o reads done

        float pred = eg * (part_p[0][c] + part_p[1][c] + part_p[2][c] + part_p[3][c]);
        float vn = bet_c * (vt_c - pred);

        const unsigned long long eg2 = pack2(eg);
        const unsigned long long vn2 = pack2(vn);

        unsigned long long o2 = 0ull;
        #pragma unroll
        for (int i = 0; i < 32; i++) {
            unsigned long long kv;
            mul2(kv, kp2[i], vn2);
            fma2(hreg[i], hreg[i], eg2, kv);
            fma2(o2, hreg[i], qp2[i], o2);
        }
        part_o[gq][c] = sum2(o2);

        tok_p = tok_c; w_p = w_c; slt_p = slt_c;
        tok_c = tok_n; w_c = w_n; slt_c = slt_n;
        gd_c = gd_n; bet_c = bet_n; vt_c = vt_n;
    }

    __syncthreads();
    if (t < 64) {
        float ov = part_o[0][c] + part_o[1][c] + part_o[2][c] + part_o[3][c];
        g_o2[(size_t)slt_p * TOKN * VDD + (size_t)tok_p * VDD + h * HVDD + vs + c]
            = w_p * ov;
    }
}

// ---------------- gated RMSNorm, fused split-bf16 output -------------------
__global__ __launch_bounds__(256) void rmsnorm_kernel(const float* __restrict__ onw)
{
    const int grp = blockIdx.x;            // tok*NH + h
    const int tok = grp >> 2;
    const int h   = grp & 3;
    const int t = threadIdx.x;
    const size_t base = (size_t)grp * HVDD;
    const size_t sstr = (size_t)TOKN * VDD;
    float v0 = g_o2[base + t]       + g_o2[sstr + base + t];
    float v1 = g_o2[base + t + 256] + g_o2[sstr + base + t + 256];
    float ss = block_sum_256(v0 * v0 + v1 * v1);
    float inv = rsqrtf(ss * (1.f / 512.f) + 1e-6f);
    float gp0 = g_GP[base + t], gp1 = g_GP[base + t + 256];
    float out0 = v0 * inv * onw[t]       / (1.f + expf(-gp0));
    float out1 = v1 * inv * onw[t + 256] / (1.f + expf(-gp1));

    __nv_bfloat16* dst = s_nr + (size_t)tok * K3;
    const int col0 = h * HVDD + t;
    const int col1 = col0 + 256;
    __nv_bfloat16 hi0 = __float2bfloat16(out0);
    __nv_bfloat16 lo0 = __float2bfloat16(out0 - __bfloat162float(hi0));
    __nv_bfloat16 hi1 = __float2bfloat16(out1);
    __nv_bfloat16 lo1 = __float2bfloat16(out1 - __bfloat162float(hi1));
    dst[col0] = hi0;  dst[VDD + col0] = lo0;  dst[2 * VDD + col0] = hi0;
    dst[col1] = hi1;  dst[VDD + col1] = lo1;  dst[2 * VDD + col1] = hi1;
}

// ---------------- launcher -------------------------------------------------
extern "C" void kernel_launch(void* const* d_in, const int* in_sizes, int n_in,
                              void* d_out, int out_size)
{
    const float* x        = (const float*)d_in[0];
    const float* gate_w   = (const float*)d_in[1];
    const float* q_w      = (const float*)d_in[2];
    const float* k_w      = (const float*)d_in[3];
    const float* v_w      = (const float*)d_in[4];
    const float* b_w      = (const float*)d_in[5];
    const float* a_w      = (const float*)d_in[6];
    const float* g_w      = (const float*)d_in[7];
    const float* o_w      = (const float*)d_in[8];
    const float* A_log    = (const float*)d_in[9];
    const float* dt_bias  = (const float*)d_in[10];
    const float* o_norm_w = (const float*)d_in[11];
    float* out = (float*)d_out;

    static cudaStream_t s1 = nullptr, s2 = nullptr;
    static cudaEvent_t evRoot = nullptr, evX = nullptr, evV = nullptr,
                       evGP = nullptr, evS2 = nullptr;
    if (s1 == nullptr) {
        cudaStreamCreateWithFlags(&s1, cudaStreamNonBlocking);
        cudaStreamCreateWithFlags(&s2, cudaStreamNonBlocking);
        cudaEventCreateWithFlags(&evRoot, cudaEventDisableTiming);
        cudaEventCreateWithFlags(&evX,    cudaEventDisableTiming);
        cudaEventCreateWithFlags(&evV,    cudaEventDisableTiming);
        cudaEventCreateWithFlags(&evGP,   cudaEventDisableTiming);
        cudaEventCreateWithFlags(&evS2,   cudaEventDisableTiming);
        cudaFuncSetAttribute(bgemm_kernel, cudaFuncAttributeMaxDynamicSharedMemorySize, DSMEM);
    }

    cudaEventRecord(evRoot, 0);
    cudaStreamWaitEvent(s1, evRoot, 0);
    cudaStreamWaitEvent(s2, evRoot, 0);

    // stream 0: QK path
    conv_kernel<<<TOKN, 256, 0, 0>>>(x, 0, 0, 0);            // s_x
    cudaEventRecord(evX, 0);
    conv_kernel<<<KDD, 256, 0, 0>>>(q_w, 2, 1, 0);
    conv_kernel<<<KDD, 256, 0, 0>>>(k_w, 2, 1, KDD);
    bgemm_kernel<<<dim3(2 * KDD / 128, TOKN / 128), 128, DSMEM, 0>>>(0, 2, 0, nullptr, 0);
    l2norm_kernel<<<dim3(TOKN * NHH, 2), 256, 0, 0>>>();

    // stream s1: V GEMM (needed by recur), then GP GEMM (needed only by rmsnorm,
    // overlaps with the latency-bound recurrence)
    conv_kernel<<<VDD, 256, 0, s1>>>(v_w, 3, 1, 0);
    conv_kernel<<<VDD, 256, 0, s1>>>(g_w, 3, 1, VDD);
    cudaStreamWaitEvent(s1, evX, 0);
    bgemm_kernel<<<dim3(VDD / 128, TOKN / 128), 128, DSMEM, s1>>>(0, 3, 1, nullptr, 0);
    cudaEventRecord(evV, s1);
    bgemm_kernel<<<dim3(VDD / 128, TOKN / 128), 128, DSMEM, s1>>>(0, 3, 3, nullptr, VDD);
    cudaEventRecord(evGP, s1);

    // stream s2: gate / routing lists / output-weight conversion
    gate_kernel<<<TOKN, 128, 0, s2>>>(x, gate_w, b_w, a_w, A_log, dt_bias);
    buildlist_kernel<<<NMM * BB, 32, 0, s2>>>();
    conv_kernel<<<HIDD, 256, 0, s2>>>(o_w, 4, 1, 0);
    cudaEventRecord(evS2, s2);

    // recurrence needs: l2norm (stream 0), V (evV), gate/lists (evS2)
    cudaStreamWaitEvent(0, evV, 0);
    cudaStreamWaitEvent(0, evS2, 0);
    recur_kernel<<<dim3(NMM * BB * NHH, HVDD / 64), 256, 0, 0>>>();

    // rmsnorm additionally needs GP
    cudaStreamWaitEvent(0, evGP, 0);
    rmsnorm_kernel<<<TOKN * NHH, 256, 0, 0>>>(o_norm_w);
    bgemm_kernel<<<dim3(HIDD / 128, TOKN / 128), 128, DSMEM, 0>>>(1, 4, 2, out, 0);
}